// round 1
// baseline (speedup 1.0000x reference)
#include <cuda_runtime.h>

#define DIMS 128
#define NVOX (128*128*128)
#define NBATCH 2
#define NELEM (NBATCH*NVOX*3)
#define INT_STEPS 7

// Static scratch buffer (allocation-free rule): one ping-pong partner for d_out.
__device__ float g_scratch[NELEM];

// ---------------------------------------------------------------------------
// Step 0: v = vel / 2^7   (vectorized float4; NELEM = 12,582,912 divisible by 4)
// ---------------------------------------------------------------------------
__global__ void scale_kernel(const float4* __restrict__ in,
                             float4* __restrict__ out, int n4) {
    int i = blockIdx.x * blockDim.x + threadIdx.x;
    if (i < n4) {
        const float s = 1.0f / 128.0f;  // 2^-7
        float4 v = in[i];
        v.x *= s; v.y *= s; v.z *= s; v.w *= s;
        out[i] = v;
    }
}

// ---------------------------------------------------------------------------
// One scaling-and-squaring step: vout = vin + trilerp(vin, grid + vin)
// Layout: [b, z, y, x, c] with c fastest; coords clipped to [0, 127].
// ---------------------------------------------------------------------------
__global__ void __launch_bounds__(256)
warp_kernel(const float* __restrict__ vin, float* __restrict__ vout) {
    int idx = blockIdx.x * blockDim.x + threadIdx.x;   // 0 .. 2*128^3-1
    int x = idx & 127;
    int y = (idx >> 7) & 127;
    int z = (idx >> 14) & 127;
    int b = idx >> 21;

    int o = idx * 3;                                   // global float offset
    float v0 = vin[o + 0];
    float v1 = vin[o + 1];
    float v2 = vin[o + 2];

    // Absolute sample coordinates, clipped (matches jnp.clip(loc, 0, dim-1))
    float lz = fminf(fmaxf((float)z + v0, 0.0f), 127.0f);
    float ly = fminf(fmaxf((float)y + v1, 0.0f), 127.0f);
    float lx = fminf(fmaxf((float)x + v2, 0.0f), 127.0f);

    float fz = floorf(lz), fy = floorf(ly), fx = floorf(lx);
    int iz0 = (int)fz, iy0 = (int)fy, ix0 = (int)fx;
    int iz1 = min(iz0 + 1, 127);
    int iy1 = min(iy0 + 1, 127);
    int ix1 = min(ix0 + 1, 127);
    float wz = lz - fz, wy = ly - fy, wx = lx - fx;

    const float* p = vin + (size_t)b * (NVOX * 3);

    int r00 = ((iz0 << 7) + iy0) << 7;   // row bases (voxel index, pre-*3)
    int r01 = ((iz0 << 7) + iy1) << 7;
    int r10 = ((iz1 << 7) + iy0) << 7;
    int r11 = ((iz1 << 7) + iy1) << 7;

    int o000 = (r00 + ix0) * 3, o001 = (r00 + ix1) * 3;
    int o010 = (r01 + ix0) * 3, o011 = (r01 + ix1) * 3;
    int o100 = (r10 + ix0) * 3, o101 = (r10 + ix1) * 3;
    int o110 = (r11 + ix0) * 3, o111 = (r11 + ix1) * 3;

    float own[3] = {v0, v1, v2};
    float res[3];
    #pragma unroll
    for (int c = 0; c < 3; c++) {
        float c000 = __ldg(p + o000 + c), c001 = __ldg(p + o001 + c);
        float c010 = __ldg(p + o010 + c), c011 = __ldg(p + o011 + c);
        float c100 = __ldg(p + o100 + c), c101 = __ldg(p + o101 + c);
        float c110 = __ldg(p + o110 + c), c111 = __ldg(p + o111 + c);
        // lerp along x
        float a00 = c000 + wx * (c001 - c000);
        float a01 = c010 + wx * (c011 - c010);
        float a10 = c100 + wx * (c101 - c100);
        float a11 = c110 + wx * (c111 - c110);
        // lerp along y
        float b0 = a00 + wy * (a01 - a00);
        float b1 = a10 + wy * (a11 - a10);
        // lerp along z, then add self (v <- v + v o (id + v))
        res[c] = own[c] + (b0 + wz * (b1 - b0));
    }

    vout[o + 0] = res[0];
    vout[o + 1] = res[1];
    vout[o + 2] = res[2];
}

// ---------------------------------------------------------------------------
extern "C" void kernel_launch(void* const* d_in, const int* in_sizes, int n_in,
                              void* d_out, int out_size) {
    const float* vel = (const float*)d_in[0];
    float* out = (float*)d_out;

    float* scratch = nullptr;
    cudaGetSymbolAddress((void**)&scratch, g_scratch);

    const int nthreads = NBATCH * NVOX;            // one thread per voxel
    const int n4 = NELEM / 4;

    // v0 = vel / 128  -> scratch
    scale_kernel<<<(n4 + 255) / 256, 256>>>((const float4*)vel,
                                            (float4*)scratch, n4);

    // 7 steps alternating scratch <-> out; odd count ends in d_out.
    const float* src = scratch;
    float* dst = out;
    for (int s = 0; s < INT_STEPS; s++) {
        warp_kernel<<<nthreads / 256, 256>>>(src, dst);
        if (s % 2 == 0) { src = out;     dst = scratch; }
        else            { src = scratch; dst = out;     }
    }
}

// round 2
// speedup vs baseline: 1.1809x; 1.1809x over previous
#include <cuda_runtime.h>

#define NVOX (128*128*128)
#define NBATCH 2
#define NELEM (NBATCH*NVOX*3)
#define NTHREADS (NBATCH*NVOX)
#define INT_STEPS 7

// Two ping-pong scratch buffers in padded float4 layout: [b][z][y][x] -> float4(xyz,0)
__device__ float4 g_bufA[NBATCH * NVOX];
__device__ float4 g_bufB[NBATCH * NVOX];

// ---------------------------------------------------------------------------
// Step 0: read packed float3 vel, scale by 2^-7, write float4 (w=0)
// ---------------------------------------------------------------------------
__global__ void __launch_bounds__(256)
scale4_kernel(const float* __restrict__ in, float4* __restrict__ out) {
    int i = blockIdx.x * blockDim.x + threadIdx.x;
    const float s = 1.0f / 128.0f;
    int o = i * 3;
    float4 v;
    v.x = in[o + 0] * s;
    v.y = in[o + 1] * s;
    v.z = in[o + 2] * s;
    v.w = 0.0f;
    out[i] = v;
}

// ---------------------------------------------------------------------------
// Trilinear gather core: res = own + trilerp(vin, grid + own)
// vin layout: float4 per voxel, [b][z][y][x], channels (z,y,x) in .x/.y/.z
// ---------------------------------------------------------------------------
__device__ __forceinline__ float4 warp_step(const float4* __restrict__ vin,
                                            int idx) {
    int x = idx & 127;
    int y = (idx >> 7) & 127;
    int z = (idx >> 14) & 127;
    int b = idx >> 21;

    float4 own = vin[idx];

    float lz = fminf(fmaxf((float)z + own.x, 0.0f), 127.0f);
    float ly = fminf(fmaxf((float)y + own.y, 0.0f), 127.0f);
    float lx = fminf(fmaxf((float)x + own.z, 0.0f), 127.0f);

    float fz = floorf(lz), fy = floorf(ly), fx = floorf(lx);
    int iz0 = (int)fz, iy0 = (int)fy, ix0 = (int)fx;
    int iz1 = min(iz0 + 1, 127);
    int iy1 = min(iy0 + 1, 127);
    int ix1 = min(ix0 + 1, 127);
    float wz = lz - fz, wy = ly - fy, wx = lx - fx;

    const float4* p = vin + b * NVOX;

    int r00 = ((iz0 << 7) + iy0) << 7;
    int r01 = ((iz0 << 7) + iy1) << 7;
    int r10 = ((iz1 << 7) + iy0) << 7;
    int r11 = ((iz1 << 7) + iy1) << 7;

    float4 c000 = __ldg(p + r00 + ix0), c001 = __ldg(p + r00 + ix1);
    float4 c010 = __ldg(p + r01 + ix0), c011 = __ldg(p + r01 + ix1);
    float4 c100 = __ldg(p + r10 + ix0), c101 = __ldg(p + r10 + ix1);
    float4 c110 = __ldg(p + r11 + ix0), c111 = __ldg(p + r11 + ix1);

    // lerp along x
    float4 a00, a01, a10, a11;
    a00.x = fmaf(wx, c001.x - c000.x, c000.x);
    a00.y = fmaf(wx, c001.y - c000.y, c000.y);
    a00.z = fmaf(wx, c001.z - c000.z, c000.z);
    a01.x = fmaf(wx, c011.x - c010.x, c010.x);
    a01.y = fmaf(wx, c011.y - c010.y, c010.y);
    a01.z = fmaf(wx, c011.z - c010.z, c010.z);
    a10.x = fmaf(wx, c101.x - c100.x, c100.x);
    a10.y = fmaf(wx, c101.y - c100.y, c100.y);
    a10.z = fmaf(wx, c101.z - c100.z, c100.z);
    a11.x = fmaf(wx, c111.x - c110.x, c110.x);
    a11.y = fmaf(wx, c111.y - c110.y, c110.y);
    a11.z = fmaf(wx, c111.z - c110.z, c110.z);

    // lerp along y
    float b0x = fmaf(wy, a01.x - a00.x, a00.x);
    float b0y = fmaf(wy, a01.y - a00.y, a00.y);
    float b0z = fmaf(wy, a01.z - a00.z, a00.z);
    float b1x = fmaf(wy, a11.x - a10.x, a10.x);
    float b1y = fmaf(wy, a11.y - a10.y, a10.y);
    float b1z = fmaf(wy, a11.z - a10.z, a10.z);

    // lerp along z + add self
    float4 res;
    res.x = own.x + fmaf(wz, b1x - b0x, b0x);
    res.y = own.y + fmaf(wz, b1y - b0y, b0y);
    res.z = own.z + fmaf(wz, b1z - b0z, b0z);
    res.w = 0.0f;
    return res;
}

// Middle steps: float4 -> float4
__global__ void __launch_bounds__(256)
step4_kernel(const float4* __restrict__ vin, float4* __restrict__ vout) {
    int idx = blockIdx.x * blockDim.x + threadIdx.x;
    vout[idx] = warp_step(vin, idx);
}

// Final step: float4 -> packed float3 into d_out
__global__ void __launch_bounds__(256)
step_final_kernel(const float4* __restrict__ vin, float* __restrict__ out) {
    int idx = blockIdx.x * blockDim.x + threadIdx.x;
    float4 r = warp_step(vin, idx);
    int o = idx * 3;
    out[o + 0] = r.x;
    out[o + 1] = r.y;
    out[o + 2] = r.z;
}

// ---------------------------------------------------------------------------
extern "C" void kernel_launch(void* const* d_in, const int* in_sizes, int n_in,
                              void* d_out, int out_size) {
    const float* vel = (const float*)d_in[0];
    float* out = (float*)d_out;

    float4 *bufA = nullptr, *bufB = nullptr;
    cudaGetSymbolAddress((void**)&bufA, g_bufA);
    cudaGetSymbolAddress((void**)&bufB, g_bufB);

    const int nblocks = NTHREADS / 256;

    // v0 = vel / 128 -> bufA (float4 layout)
    scale4_kernel<<<nblocks, 256>>>(vel, bufA);

    // Steps 1..6: ping-pong float4 buffers
    const float4* src = bufA;
    float4* dst = bufB;
    for (int s = 0; s < INT_STEPS - 1; s++) {
        step4_kernel<<<nblocks, 256>>>(src, dst);
        const float4* t = dst;
        dst = (float4*)src;
        src = t;
    }

    // Step 7: final, write packed float3 to d_out
    step_final_kernel<<<nblocks, 256>>>(src, out);
}